// round 1
// baseline (speedup 1.0000x reference)
#include <cuda_runtime.h>

// Hierarchical softmax CE loss.
// Tree: BRANCH=10, DEPTH=3, N_LVL=[10,100,1000], OFFSET=[0,10,110,1110].
// Every sibling group is 10 contiguous nodes. For target leaf l:
//   path nodes: a0 = l/100 ; a1 = 10 + l/10 ; leaf = 110 + l
//   their groups (contiguous 10-node spans):
//     [0,10) ; [10 + 10*(l/100), +10) ; [110 + 10*(l/10), +10)
// loss = -mean_b( sum over 3 path nodes of w[node] * logsoftmax_within_group )

#define BATCH   65536
#define NNODES  1110
#define TPB     256
#define NBLOCKS (BATCH / TPB)   // 256

__device__ float g_partials[NBLOCKS];

__device__ __forceinline__ float seg_term(const float* __restrict__ xr,
                                          const float* __restrict__ w,
                                          int base, int sel) {
    float v[10];
#pragma unroll
    for (int i = 0; i < 10; i++) v[i] = __ldg(xr + base + i);
    float m = v[0];
#pragma unroll
    for (int i = 1; i < 10; i++) m = fmaxf(m, v[i]);
    float s = 0.0f;
#pragma unroll
    for (int i = 0; i < 10; i++) s += expf(v[i] - m);
    // selected value: re-load (L1 hit) to avoid dynamic register indexing
    float xv = __ldg(xr + sel);
    float lp = xv - m - logf(s);
    return __ldg(w + sel) * lp;
}

__global__ void __launch_bounds__(TPB)
hsm_loss_kernel(const float* __restrict__ x,
                const float* __restrict__ w,
                const int* __restrict__ target) {
    const int row = blockIdx.x * TPB + threadIdx.x;  // grid sized exactly to BATCH
    const float* xr = x + (size_t)row * NNODES;
    const int l  = __ldg(target + row);
    const int j  = l / 10;     // level-1 local index
    const int a0 = l / 100;    // level-0 ancestor

    float acc = seg_term(xr, w, 0,            a0)
              + seg_term(xr, w, 10 + 10 * a0, 10 + j)
              + seg_term(xr, w, 110 + 10 * j, 110 + l);

    // block reduction (deterministic)
    __shared__ float sm[TPB];
    sm[threadIdx.x] = acc;
    __syncthreads();
#pragma unroll
    for (int s = TPB / 2; s > 32; s >>= 1) {
        if (threadIdx.x < s) sm[threadIdx.x] += sm[threadIdx.x + s];
        __syncthreads();
    }
    if (threadIdx.x < 32) {
        float v = sm[threadIdx.x] + sm[threadIdx.x + 32];
#pragma unroll
        for (int o = 16; o > 0; o >>= 1)
            v += __shfl_down_sync(0xFFFFFFFFu, v, o);
        if (threadIdx.x == 0) g_partials[blockIdx.x] = v;
    }
}

__global__ void __launch_bounds__(NBLOCKS)
hsm_final_kernel(float* __restrict__ out) {
    __shared__ float sm[NBLOCKS];
    sm[threadIdx.x] = g_partials[threadIdx.x];
    __syncthreads();
#pragma unroll
    for (int s = NBLOCKS / 2; s > 32; s >>= 1) {
        if (threadIdx.x < s) sm[threadIdx.x] += sm[threadIdx.x + s];
        __syncthreads();
    }
    if (threadIdx.x < 32) {
        float v = sm[threadIdx.x] + sm[threadIdx.x + 32];
#pragma unroll
        for (int o = 16; o > 0; o >>= 1)
            v += __shfl_down_sync(0xFFFFFFFFu, v, o);
        if (threadIdx.x == 0) out[0] = -v / (float)BATCH;
    }
}

extern "C" void kernel_launch(void* const* d_in, const int* in_sizes, int n_in,
                              void* d_out, int out_size) {
    // metadata order: inputs [B,N] f32, weights [1,N] f32, target [B] i32,
    //                 segment_ids [N] i32 (unused), path_indices [1000,3] i32 (unused)
    const float* x      = (const float*)d_in[0];
    const float* w      = (const float*)d_in[1];
    const int*   target = (const int*)d_in[2];
    float* out = (float*)d_out;

    hsm_loss_kernel<<<NBLOCKS, TPB>>>(x, w, target);
    hsm_final_kernel<<<1, NBLOCKS>>>(out);
}

// round 2
// speedup vs baseline: 1.2610x; 1.2610x over previous
#include <cuda_runtime.h>

// Hierarchical softmax CE loss — fused single-kernel version.
// Tree: BRANCH=10, DEPTH=3, OFFSET=[0,10,110,1110]; groups are 10 contiguous nodes.
// For target leaf l: groups [0,10) sel a0=l/100 ; [10+10*a0,+10) sel j%10 (j=l/10) ;
// [110+10*j,+10) sel l%10.  loss = -mean_b sum_path w[node]*logsoftmax_in_group.

#define BATCH   65536
#define NNODES  1110
#define TPB     128
#define NBLOCKS (BATCH / TPB)   // 512

__device__ float    g_partials[NBLOCKS];
__device__ unsigned g_ticket = 0;

// One 10-wide sibling group starting at even node index `base` (float2-aligned).
// Returns w[base+loc] * (x[base+loc] - max - log(sum exp(x-max))).
__device__ __forceinline__ float seg_term(const float* __restrict__ xr,
                                          const float* __restrict__ w,
                                          int base, int loc) {
    const float2* q = reinterpret_cast<const float2*>(xr + base);
    float v[10];
#pragma unroll
    for (int i = 0; i < 5; i++) {
        float2 p = __ldg(q + i);
        v[2 * i]     = p.x;
        v[2 * i + 1] = p.y;
    }
    float m = v[0];
#pragma unroll
    for (int i = 1; i < 10; i++) m = fmaxf(m, v[i]);
    float s = 0.0f;
#pragma unroll
    for (int i = 0; i < 10; i++) s += expf(v[i] - m);
    // register select of the target node's value (no extra memory op)
    float xv = v[0];
#pragma unroll
    for (int i = 1; i < 10; i++) xv = (loc == i) ? v[i] : xv;
    return __ldg(w + base + loc) * (xv - m - logf(s));
}

__global__ void __launch_bounds__(TPB)
hsm_fused_kernel(const float* __restrict__ x,
                 const float* __restrict__ w,
                 const int* __restrict__ target,
                 float* __restrict__ out) {
    const int row = blockIdx.x * TPB + threadIdx.x;   // grid exactly covers BATCH
    const float* xr = x + (size_t)row * NNODES;
    const int l  = __ldg(target + row);
    const int j  = l / 10;
    const int a0 = l / 100;

    float acc = seg_term(xr, w, 0,            a0)
              + seg_term(xr, w, 10 + 10 * a0, j - 10 * a0)
              + seg_term(xr, w, 110 + 10 * j, l - 10 * j);

    // ---- deterministic block reduction ----
    __shared__ float sm[TPB];
    sm[threadIdx.x] = acc;
    __syncthreads();
#pragma unroll
    for (int s = TPB / 2; s > 32; s >>= 1) {
        if (threadIdx.x < s) sm[threadIdx.x] += sm[threadIdx.x + s];
        __syncthreads();
    }
    __shared__ bool s_last;
    if (threadIdx.x < 32) {
        float v = sm[threadIdx.x] + sm[threadIdx.x + 32];
#pragma unroll
        for (int o = 16; o > 0; o >>= 1)
            v += __shfl_down_sync(0xFFFFFFFFu, v, o);
        if (threadIdx.x == 0) {
            g_partials[blockIdx.x] = v;
            __threadfence();
            unsigned t = atomicAdd(&g_ticket, 1u);
            s_last = (t == NBLOCKS - 1);
        }
    }
    __syncthreads();

    // ---- last block finishes: deterministic fixed-order sum of partials ----
    if (s_last) {
        float v = 0.0f;
#pragma unroll
        for (int k = 0; k < NBLOCKS / TPB; k++)           // 4 per thread, fixed order
            v += g_partials[threadIdx.x + k * TPB];
        sm[threadIdx.x] = v;
        __syncthreads();
#pragma unroll
        for (int s = TPB / 2; s > 32; s >>= 1) {
            if (threadIdx.x < s) sm[threadIdx.x] += sm[threadIdx.x + s];
            __syncthreads();
        }
        if (threadIdx.x < 32) {
            float r = sm[threadIdx.x] + sm[threadIdx.x + 32];
#pragma unroll
            for (int o = 16; o > 0; o >>= 1)
                r += __shfl_down_sync(0xFFFFFFFFu, r, o);
            if (threadIdx.x == 0) {
                out[0] = -r / (float)BATCH;
                g_ticket = 0;                              // reset for next graph replay
            }
        }
    }
}

extern "C" void kernel_launch(void* const* d_in, const int* in_sizes, int n_in,
                              void* d_out, int out_size) {
    const float* x      = (const float*)d_in[0];
    const float* w      = (const float*)d_in[1];
    const int*   target = (const int*)d_in[2];
    float* out = (float*)d_out;

    hsm_fused_kernel<<<NBLOCKS, TPB>>>(x, w, target, out);
}